// round 2
// baseline (speedup 1.0000x reference)
#include <cuda_runtime.h>

#define NN   25000
#define EE   400000
#define FIN  256
#define CC   32
#define AA   9
#define WN   288     // CC*AA
#define BB   8
#define HH   64
#define SSP  4
#define FOUT 256

__device__ float g_h[NN * CC];      // 3.2 MB
__device__ float g_agg[NN * WN];    // 28.8 MB

__device__ __forceinline__ float silu_f(float v) {
    return v / (1.0f + __expf(-v));
}

// ---- packed f32x2 helpers (sm_103a FFMA2) ----
__device__ __forceinline__ void fma2(unsigned long long& acc, unsigned long long a,
                                     unsigned long long b) {
    asm("fma.rn.f32x2 %0, %1, %2, %0;" : "+l"(acc) : "l"(a), "l"(b));
}
__device__ __forceinline__ unsigned long long pack2(float x, float y) {
    unsigned long long r;
    asm("mov.b64 %0, {%1, %2};" : "=l"(r) : "f"(x), "f"(y));
    return r;
}
__device__ __forceinline__ float2 unpack2(unsigned long long v) {
    float2 r;
    asm("mov.b64 {%0, %1}, %2;" : "=f"(r.x), "=f"(r.y) : "l"(v));
    return r;
}
__device__ __forceinline__ unsigned long long lds64(const float* p) {
    return *reinterpret_cast<const unsigned long long*>(p);
}

// ---------------------------------------------------------------------------
__global__ void k_zero() {
    int i = blockIdx.x * blockDim.x + threadIdx.x;
    int stride = gridDim.x * blockDim.x;
    float4* p = (float4*)g_agg;
    const int n4 = (NN * WN) / 4;
    float4 z = make_float4(0.f, 0.f, 0.f, 0.f);
    for (; i < n4; i += stride) p[i] = z;
}

// ---------------------------------------------------------------------------
// h = 0.25 * (x @ W1)    [NN, CC]
// ---------------------------------------------------------------------------
__global__ void __launch_bounds__(256) k_h(const float* __restrict__ x,
                                           const float* __restrict__ W1) {
    __shared__ float sW1[FIN * CC];
    __shared__ float sX[8][FIN];
    int t = threadIdx.x;
    int n0 = blockIdx.x * 8;
    for (int i = t; i < FIN * CC; i += 256) sW1[i] = W1[i];
    for (int i = t; i < 8 * FIN; i += 256)
        sX[i >> 8][i & 255] = x[(n0 + (i >> 8)) * FIN + (i & 255)];
    __syncthreads();
    int ty = t >> 5, tx = t & 31;
    float acc = 0.f;
#pragma unroll 8
    for (int f = 0; f < FIN; f++) acc += sX[ty][f] * sW1[f * CC + tx];
    g_h[(n0 + ty) * CC + tx] = 0.25f * acc;
}

// ---------------------------------------------------------------------------
// sc_out GEMM: out[n,o] = sum_k xa[n,k] * WscFlat[k,o], K=1024
// tile 64 x 128, block 256, micro 4x8, packed f32x2
// ---------------------------------------------------------------------------
__global__ void __launch_bounds__(256) k_sc(const float* __restrict__ x,
                                            const float* __restrict__ attrs,
                                            const float* __restrict__ Wsc,
                                            float* __restrict__ out) {
    __shared__ float sA[32][64];
    __shared__ float sB[32][128];
    int t = threadIdx.x;
    int n0 = blockIdx.x * 64;
    int o0 = blockIdx.y * 128;
    int tr = t & 15;    // node group (broadcast-friendly B reads)
    int tc = t >> 4;    // out group
    unsigned long long acc2[4][4];
#pragma unroll
    for (int i = 0; i < 4; i++)
#pragma unroll
        for (int j = 0; j < 4; j++) acc2[i][j] = 0ull;

    for (int kc = 0; kc < FIN * SSP; kc += 32) {
        for (int i = t; i < 32 * 64; i += 256) {
            int kk = i >> 6, n = i & 63;
            int k = kc + kk;
            int nn = n0 + n;
            float v = 0.f;
            if (nn < NN) v = x[nn * FIN + (k >> 2)] * attrs[nn * SSP + (k & 3)];
            sA[kk][n] = v;
        }
        for (int i = t; i < 32 * 128; i += 256) {
            int kk = i >> 7, o = i & 127;
            sB[kk][o] = Wsc[(kc + kk) * FOUT + o0 + o];
        }
        __syncthreads();
#pragma unroll 4
        for (int k = 0; k < 32; k++) {
            float4 av = *(const float4*)&sA[k][tr * 4];
            unsigned long long b2[4];
#pragma unroll
            for (int j = 0; j < 4; j++) b2[j] = lds64(&sB[k][tc * 8 + 2 * j]);
            float a_[4] = {av.x, av.y, av.z, av.w};
#pragma unroll
            for (int i = 0; i < 4; i++) {
                unsigned long long aa = pack2(a_[i], a_[i]);
#pragma unroll
                for (int j = 0; j < 4; j++) fma2(acc2[i][j], aa, b2[j]);
            }
        }
        __syncthreads();
    }
#pragma unroll
    for (int i = 0; i < 4; i++) {
        int nn = n0 + tr * 4 + i;
        if (nn >= NN) continue;
        float2 r0 = unpack2(acc2[i][0]);
        float2 r1 = unpack2(acc2[i][1]);
        float2 r2 = unpack2(acc2[i][2]);
        float2 r3 = unpack2(acc2[i][3]);
        float4 lo = make_float4(r0.x, r0.y, r1.x, r1.y);
        float4 hi = make_float4(r2.x, r2.y, r3.x, r3.y);
        *(float4*)&out[nn * FOUT + o0 + tc * 8] = lo;
        *(float4*)&out[nn * FOUT + o0 + tc * 8 + 4] = hi;
    }
}

// ---------------------------------------------------------------------------
// fused edge kernel: radial MLP -> TP weights -> message -> vectorized scatter
// ---------------------------------------------------------------------------
#define ACTP 68   // sAct row stride (16B aligned for float4 over k)

__global__ void __launch_bounds__(256, 1) k_edge(
    const float* __restrict__ eeG, const float* __restrict__ shG,
    const int* __restrict__ dstG, const int* __restrict__ srcG,
    const float* __restrict__ Wm1, const float* __restrict__ Wm2,
    const float* __restrict__ Wm3) {
    extern __shared__ float sm[];
    float* sWm1 = sm;                    // 512
    float* sWm2 = sWm1 + 512;            // 4096
    float* sWm3 = sWm2 + 4096;           // 18432
    float* sAct = sWm3 + 18432;          // 64*68 = 4352
    float* sEE  = sAct + 64 * ACTP;      // 512
    float* sSH  = sEE + 512;             // 576
    float* sHs  = sSH + 576;             // 2048
    int*   sDst = (int*)(sHs + 2048);    // 64
    int*   sSrc = sDst + 64;             // 64

    int t = threadIdx.x;
    for (int i = t; i < 512;   i += 256) sWm1[i] = Wm1[i];
    for (int i = t; i < 4096;  i += 256) sWm2[i] = Wm2[i];
    for (int i = t; i < 18432; i += 256) sWm3[i] = Wm3[i];
    __syncthreads();

    const int tx = t & 31, ty = t >> 5;
    const int e2 = t >> 2;          // 0..63 (phase 1/2 edge)
    const int j02 = (t & 3) * 16;   // phase 1/2 output group

    // per-thread output (c,a) decomposition for the packed scatter
    int c0[5], a0i[5], c1[5], a1i[5];
#pragma unroll
    for (int jj = 0; jj < 5; jj++) {
        int o0 = 2 * tx + 64 * jj;
        c0[jj] = o0 / 9; a0i[jj] = o0 - 9 * c0[jj];
        int o1 = o0 + 1;
        c1[jj] = o1 / 9; a1i[jj] = o1 - 9 * c1[jj];
    }

    for (int tile = blockIdx.x; tile < EE / 64; tile += gridDim.x) {
        int e0 = tile * 64;
        for (int i = t; i < 64 * BB; i += 256) sEE[i] = eeG[e0 * BB + i];
        for (int i = t; i < 64 * AA; i += 256) sSH[i] = shG[e0 * AA + i];
        if (t < 64) { sDst[t] = dstG[e0 + t]; sSrc[t] = srcG[e0 + t]; }
        __syncthreads();

        for (int i = t; i < 64 * CC; i += 256) {
            int e = i >> 5, c = i & 31;
            sHs[i] = g_h[sSrc[e] * CC + c];
        }

        // phase 1: h1 = silu(ee @ Wm1) — thread: 1 edge x 16 outs
        {
            float acc[16];
#pragma unroll
            for (int j = 0; j < 16; j++) acc[j] = 0.f;
#pragma unroll
            for (int b = 0; b < BB; b++) {
                float v = sEE[e2 * BB + b];
#pragma unroll
                for (int j = 0; j < 16; j++) acc[j] += v * sWm1[b * HH + j02 + j];
            }
#pragma unroll
            for (int j = 0; j < 16; j++) sAct[e2 * ACTP + j02 + j] = silu_f(acc[j]);
        }
        __syncthreads();

        // phase 2: h2 = silu(h1 @ Wm2) — packed f32x2
        {
            unsigned long long acc2p[8];
#pragma unroll
            for (int jp = 0; jp < 8; jp++) acc2p[jp] = 0ull;
#pragma unroll 8
            for (int k = 0; k < HH; k++) {
                float v = sAct[e2 * ACTP + k];
                unsigned long long aa = pack2(v, v);
#pragma unroll
                for (int jp = 0; jp < 8; jp++)
                    fma2(acc2p[jp], aa, lds64(&sWm2[k * HH + j02 + 2 * jp]));
            }
            __syncthreads();
#pragma unroll
            for (int jp = 0; jp < 8; jp++) {
                float2 r = unpack2(acc2p[jp]);
                sAct[e2 * ACTP + j02 + 2 * jp]     = silu_f(r.x);
                sAct[e2 * ACTP + j02 + 2 * jp + 1] = silu_f(r.y);
            }
        }
        __syncthreads();

        // phase 3: w = h2 @ Wm3, TP epilogue, red.v2 scatter
        // thread: 8 edges (e=ty+8i) x pairs o = {2tx+64jj, +1}
        {
            unsigned long long acc2[8][5];
#pragma unroll
            for (int i = 0; i < 8; i++)
#pragma unroll
                for (int jj = 0; jj < 5; jj++) acc2[i][jj] = 0ull;

            for (int k = 0; k < HH; k += 4) {
                float4 a4[8];
#pragma unroll
                for (int i = 0; i < 8; i++)
                    a4[i] = *(const float4*)&sAct[(ty + 8 * i) * ACTP + k];
#pragma unroll
                for (int kk = 0; kk < 4; kk++) {
                    unsigned long long b2[5];
#pragma unroll
                    for (int jj = 0; jj < 5; jj++)
                        if (jj < 4 || tx < 16)
                            b2[jj] = lds64(&sWm3[(k + kk) * WN + 2 * tx + 64 * jj]);
#pragma unroll
                    for (int i = 0; i < 8; i++) {
                        float av = (kk == 0) ? a4[i].x : (kk == 1) ? a4[i].y
                                 : (kk == 2) ? a4[i].z : a4[i].w;
                        unsigned long long aa = pack2(av, av);
#pragma unroll
                        for (int jj = 0; jj < 5; jj++)
                            if (jj < 4 || tx < 16) fma2(acc2[i][jj], aa, b2[jj]);
                    }
                }
            }

#pragma unroll
            for (int i = 0; i < 8; i++) {
                int e = ty + 8 * i;
                const float* hs = &sHs[e * CC];
                const float* sh = &sSH[e * AA];
                float* dst = g_agg + (long long)sDst[e] * WN;
#pragma unroll
                for (int jj = 0; jj < 5; jj++) {
                    if (jj < 4 || tx < 16) {
                        float2 w = unpack2(acc2[i][jj]);
                        float m0 = w.x * hs[c0[jj]] * sh[a0i[jj]];
                        float m1 = w.y * hs[c1[jj]] * sh[a1i[jj]];
                        asm volatile("red.global.add.v2.f32 [%0], {%1, %2};"
                                     :: "l"(dst + 2 * tx + 64 * jj),
                                        "f"(m0), "f"(m1) : "memory");
                    }
                }
            }
        }
        __syncthreads();
    }
}

// ---------------------------------------------------------------------------
// out = silu(agg @ W2) + sc_out, tile 64x64, micro 4x4, packed
// ---------------------------------------------------------------------------
__global__ void __launch_bounds__(256) k_final(const float* __restrict__ W2,
                                               float* __restrict__ out) {
    __shared__ float sA[32 * 68];   // [kk][n], stride 68 (16B aligned)
    __shared__ float sB[32][64];
    int t = threadIdx.x;
    int n0 = blockIdx.x * 64;
    int o0 = blockIdx.y * 64;
    int tr = t & 15, tc = t >> 4;
    unsigned long long acc2[4][2];
#pragma unroll
    for (int i = 0; i < 4; i++) { acc2[i][0] = 0ull; acc2[i][1] = 0ull; }

    for (int kc = 0; kc < WN; kc += 32) {
        for (int i = t; i < 64 * 32; i += 256) {
            int n = i >> 5, kk = i & 31;
            int nn = n0 + n;
            sA[kk * 68 + n] = (nn < NN) ? g_agg[(long long)nn * WN + kc + kk] : 0.f;
        }
        for (int i = t; i < 32 * 64; i += 256) {
            int kk = i >> 6, o = i & 63;
            sB[kk][o] = W2[(kc + kk) * FOUT + o0 + o];
        }
        __syncthreads();
#pragma unroll 4
        for (int k = 0; k < 32; k++) {
            float4 av = *(const float4*)&sA[k * 68 + tr * 4];
            unsigned long long b2[2];
            b2[0] = lds64(&sB[k][tc * 4]);
            b2[1] = lds64(&sB[k][tc * 4 + 2]);
            float a_[4] = {av.x, av.y, av.z, av.w};
#pragma unroll
            for (int i = 0; i < 4; i++) {
                unsigned long long aa = pack2(a_[i], a_[i]);
                fma2(acc2[i][0], aa, b2[0]);
                fma2(acc2[i][1], aa, b2[1]);
            }
        }
        __syncthreads();
    }
#pragma unroll
    for (int i = 0; i < 4; i++) {
        int nn = n0 + tr * 4 + i;
        if (nn >= NN) continue;
        float2 r0 = unpack2(acc2[i][0]);
        float2 r1 = unpack2(acc2[i][1]);
        float4 prev = *(const float4*)&out[nn * FOUT + o0 + tc * 4];
        float4 r;
        r.x = silu_f(r0.x) + prev.x;
        r.y = silu_f(r0.y) + prev.y;
        r.z = silu_f(r1.x) + prev.z;
        r.w = silu_f(r1.y) + prev.w;
        *(float4*)&out[nn * FOUT + o0 + tc * 4] = r;
    }
}

// ---------------------------------------------------------------------------
extern "C" void kernel_launch(void* const* d_in, const int* in_sizes, int n_in,
                              void* d_out, int out_size) {
    const float* x     = (const float*)d_in[0];
    const float* attrs = (const float*)d_in[1];
    const float* ee    = (const float*)d_in[2];
    const float* sh    = (const float*)d_in[3];
    const int*   eidx  = (const int*)d_in[4];
    const float* W1    = (const float*)d_in[5];
    const float* Wm1   = (const float*)d_in[6];
    const float* Wm2   = (const float*)d_in[7];
    const float* Wm3   = (const float*)d_in[8];
    const float* W2    = (const float*)d_in[9];
    const float* Wsc   = (const float*)d_in[10];
    float* out = (float*)d_out;

    const int* dst = eidx;        // edge_index[0]
    const int* src = eidx + EE;   // edge_index[1]

    k_zero<<<1024, 256>>>();
    k_h<<<NN / 8, 256>>>(x, W1);

    dim3 gsc((NN + 63) / 64, 2);
    k_sc<<<gsc, 256>>>(x, attrs, Wsc, out);

    const int edge_smem = (512 + 4096 + 18432 + 64 * ACTP + 512 + 576 + 2048) * 4 + 128 * 4;
    cudaFuncSetAttribute(k_edge, cudaFuncAttributeMaxDynamicSharedMemorySize, edge_smem);
    k_edge<<<152, 256, edge_smem>>>(ee, sh, dst, src, Wm1, Wm2, Wm3);

    dim3 gf((NN + 63) / 64, 4);
    k_final<<<gf, 256>>>(W2, out);
}